// round 9
// baseline (speedup 1.0000x reference)
#include <cuda_runtime.h>
#include <math_constants.h>

// AutoCorrelation (Autoformer): q,k,v (32,8,2048,64) fp32.
// corr[r,d] = sum_j q[r,j]*k[r,(j-d)%64]; top-4 over d, softmax, gather v.
// out = [ V (B,H,L,E) | corr^T (B,E,H,L) ]
//
// R2 base (one thread = one row, kr[64] resident, 12 warps/SM) with the
// issue-stall fix: 16 accumulators (frees 16 regs of scheduling slack under
// the same 170-reg cap) + q streamed via LDS.128 with rotating prefetch
// (64 -> 16 latency events per pass, each amortized over 64 FMAs).

#define STRS 132  // floats per tile row: 16B-aligned, LDS.128 conflict-free

// topk insert, strict > keeps lowest index on ties (lax.top_k order)
#define TOPK_INS(vv, d)                                                          \
    if (vv > w3) {                                                               \
        if (vv > w2) {                                                           \
            if (vv > w1) {                                                       \
                if (vv > w0) { w3=w2;i3=i2; w2=w1;i2=i1; w1=w0;i1=i0; w0=vv;i0=d;}\
                else          { w3=w2;i3=i2; w2=w1;i2=i1; w1=vv;i1=d; }          \
            } else            { w3=w2;i3=i2; w2=vv;i2=d; }                       \
        } else                { w3=vv;i3=d; }                                    \
    }

__global__ void __launch_bounds__(64, 6)
autocorr_kernel(const float* __restrict__ gq,
                const float* __restrict__ gk,
                const float* __restrict__ gv,
                float* __restrict__ outV,
                float* __restrict__ outC) {
    __shared__ float tile[2][32][STRS];      // one tile per warp, reused k->q->v

    const int w    = threadIdx.x >> 5;
    const int lane = threadIdx.x & 31;
    float* Tf = &tile[w][0][0];

    const long long r0  = ((long long)blockIdx.x * 2 + w) * 32;  // 32 rows/warp
    const long long off = r0 * 64;

    // stage 32 rows x 64 floats: coalesced LDG, conflict-free STS
    // (bank = (4*row + col) % 32 distinct per lane within an iteration)
#define STAGE(gsrc)                                                          \
    _Pragma("unroll 8")                                                      \
    for (int it = 0; it < 64; it++) {                                        \
        Tf[(it >> 1) * STRS + ((it & 1) << 5) + lane]                        \
            = gsrc[off + it * 32 + lane];                                    \
    }
    // doubled variant for v: also mirror into cols 64..127 (wrap-free gather)
#define STAGE2(gsrc)                                                         \
    _Pragma("unroll 8")                                                      \
    for (int it = 0; it < 64; it++) {                                        \
        const float val = gsrc[off + it * 32 + lane];                        \
        const int   c   = ((it & 1) << 5) + lane;                            \
        Tf[(it >> 1) * STRS + c]      = val;                                 \
        Tf[(it >> 1) * STRS + c + 64] = val;                                 \
    }

    // ---- k: stage, pull row into 64 regs via LDS.128 ----
    STAGE(gk);
    __syncwarp();
    float kr[64];
    {
        const float4* Kr = (const float4*)(Tf + lane * STRS);
        #pragma unroll
        for (int t = 0; t < 16; t++) {
            float4 f = Kr[t];
            kr[4*t] = f.x; kr[4*t+1] = f.y; kr[4*t+2] = f.z; kr[4*t+3] = f.w;
        }
    }
    __syncwarp();

    // ---- q into the same tile ----
    STAGE(gq);
    __syncwarp();

    // ---- top-4 state ----
    float w0=-CUDART_INF_F, w1=-CUDART_INF_F, w2=-CUDART_INF_F, w3=-CUDART_INF_F;
    int   i0=0, i1=0, i2=0, i3=0;

    // corr^T: rows of this warp share (b,h); l = l0 + lane
    const int b = (int)(r0 >> 14);
    const int h = ((int)(r0 >> 11)) & 7;
    const int l = ((int)(r0 & 2047)) + lane;
    float* cA = outC + (long long)b * (64 * 8 * 2048) + (long long)h * 2048 + l;

    // ---- correlation: 4 passes x 16 accs; q via LDS.128 + rotating prefetch ----
    const float4* Qr = (const float4*)(Tf + lane * STRS);
    #pragma unroll
    for (int p = 0; p < 4; p++) {
        float c[16];
        #pragma unroll
        for (int dd = 0; dd < 16; dd++) c[dd] = 0.f;

        float4 cur = Qr[0];
        #pragma unroll
        for (int t = 0; t < 16; t++) {
            const float4 nxt = (t < 15) ? Qr[t + 1] : cur;   // prefetch next 4 q
            #pragma unroll
            for (int s = 0; s < 4; s++) {
                const int   j  = 4 * t + s;
                const float qj = (&cur.x)[s];
                #pragma unroll
                for (int dd = 0; dd < 16; dd++)
                    c[dd] = fmaf(qj, kr[(j + 64 - p * 16 - dd) & 63], c[dd]);
            }
            cur = nxt;
        }

        #pragma unroll
        for (int dd = 0; dd < 16; dd++) {
            const int d = p * 16 + dd;
            const float v = c[dd];
            cA[d * 16384] = v;                   // lanes contiguous in l
            TOPK_INS(v, d);
        }
    }

    // ---- softmax over the 4 weights (w0 is the max) ----
    const float e1 = __expf(w1 - w0), e2 = __expf(w2 - w0), e3 = __expf(w3 - w0);
    const float inv = 1.f / (1.f + e1 + e2 + e3);
    const float t0 = inv, t1 = e1 * inv, t2 = e2 * inv, t3 = e3 * inv;

    // ---- v staged doubled (q dead) ----
    __syncwarp();
    STAGE2(gv);
    __syncwarp();

    // ---- wrap-free gather + direct float4 V store ----
    {
        const float* vp0 = Tf + lane * STRS + i0;
        const float* vp1 = Tf + lane * STRS + i1;
        const float* vp2 = Tf + lane * STRS + i2;
        const float* vp3 = Tf + lane * STRS + i3;
        float* outR = outV + off + lane * 64;
        #pragma unroll
        for (int eg = 0; eg < 16; eg++) {
            float4 o;
            #pragma unroll
            for (int s = 0; s < 4; s++) {
                const int e = eg * 4 + s;
                float sa =      t0 * vp0[e];
                sa = fmaf(t1, vp1[e], sa);
                sa = fmaf(t2, vp2[e], sa);
                sa = fmaf(t3, vp3[e], sa);
                (&o.x)[s] = sa;
            }
            *(float4*)(outR + eg * 4) = o;
        }
    }
}

extern "C" void kernel_launch(void* const* d_in, const int* in_sizes, int n_in,
                              void* d_out, int out_size) {
    const float* q = (const float*)d_in[0];
    const float* k = (const float*)d_in[1];
    const float* v = (const float*)d_in[2];
    float* outV = (float*)d_out;
    float* outC = (float*)d_out + (long long)32 * 8 * 2048 * 64;

    const int rows    = 32 * 8 * 2048;      // 524288
    const int nblocks = rows / 64;          // 8192 blocks, 2 warps (64 rows) each
    autocorr_kernel<<<nblocks, 64>>>(q, k, v, outV, outC);
}

// round 10
// speedup vs baseline: 1.0925x; 1.0925x over previous
#include <cuda_runtime.h>
#include <math_constants.h>

// AutoCorrelation (Autoformer): q,k,v (32,8,2048,64) fp32.
// corr[r,d] = sum_j q[r,j]*k[r,(j-d)%64]; top-4 over d, softmax, gather v.
// out = [ V (B,H,L,E) | corr^T (B,E,H,L) ]
//
// One thread = one row. BOTH q and k register-resident (the corr loop is a
// pure FFMA stream, no smem dependency) -> a lone warp sustains rt=2 FMA
// issue; 2.5 warps/SMSP at (64,5)/204 regs saturate the fma pipe.
// v prefetched via cp.async (no register cost) behind the corr phase.

#define STRS 68   // floats per tile row = 17 float4: 16B aligned, phase-conflict-free

#define CP_ASYNC4(smem_u32, gptr) \
    asm volatile("cp.async.ca.shared.global [%0], [%1], 4;" \
                 :: "r"(smem_u32), "l"(gptr) : "memory")
#define CP_COMMIT()  asm volatile("cp.async.commit_group;" ::: "memory")
#define CP_WAIT(N)   asm volatile("cp.async.wait_group %0;" :: "n"(N) : "memory")

// topk insert, strict > keeps lowest index on ties (lax.top_k order)
#define TOPK_INS(vv, d)                                                          \
    if (vv > w3) {                                                               \
        if (vv > w2) {                                                           \
            if (vv > w1) {                                                       \
                if (vv > w0) { w3=w2;i3=i2; w2=w1;i2=i1; w1=w0;i1=i0; w0=vv;i0=d;}\
                else          { w3=w2;i3=i2; w2=w1;i2=i1; w1=vv;i1=d; }          \
            } else            { w3=w2;i3=i2; w2=vv;i2=d; }                       \
        } else                { w3=vv;i3=d; }                                    \
    }

__global__ void __launch_bounds__(64, 5)
autocorr_kernel(const float* __restrict__ gq,
                const float* __restrict__ gk,
                const float* __restrict__ gv,
                float* __restrict__ outV,
                float* __restrict__ outC) {
    __shared__ __align__(16) float tile[2][32][STRS];  // one tile/warp: k -> q -> v

    const int w    = threadIdx.x >> 5;
    const int lane = threadIdx.x & 31;
    float* Tf = &tile[w][0][0];
    const unsigned Ts = (unsigned)__cvta_generic_to_shared(Tf);

    const long long r0  = ((long long)blockIdx.x * 2 + w) * 32;  // 32 rows/warp
    const long long off = r0 * 64;

    // stage 32 rows x 64 floats: coalesced LDG, conflict-free STS
#define STAGE(gsrc)                                                          \
    _Pragma("unroll 8")                                                      \
    for (int it = 0; it < 64; it++) {                                        \
        Tf[(it >> 1) * STRS + ((it & 1) << 5) + lane]                        \
            = gsrc[off + it * 32 + lane];                                    \
    }

    // ---- k: stage, pull row into 64 regs (LDS.128) ----
    STAGE(gk);
    __syncwarp();
    float kr[64];
    {
        const float4* P = (const float4*)(Tf + lane * STRS);
        #pragma unroll
        for (int t = 0; t < 16; t++) {
            float4 f = P[t];
            kr[4*t] = f.x; kr[4*t+1] = f.y; kr[4*t+2] = f.z; kr[4*t+3] = f.w;
        }
    }
    __syncwarp();

    // ---- q: stage, pull row into 64 regs ----
    STAGE(gq);
    __syncwarp();
    float qr[64];
    {
        const float4* P = (const float4*)(Tf + lane * STRS);
        #pragma unroll
        for (int t = 0; t < 16; t++) {
            float4 f = P[t];
            qr[4*t] = f.x; qr[4*t+1] = f.y; qr[4*t+2] = f.z; qr[4*t+3] = f.w;
        }
    }
    __syncwarp();

    // ---- v prefetch into the (now dead) tile; hides behind corr ----
    #pragma unroll 8
    for (int it = 0; it < 64; it++) {
        const int fi = (it >> 1) * STRS + ((it & 1) << 5) + lane;
        CP_ASYNC4(Ts + 4u * fi, gv + off + it * 32 + lane);
    }
    CP_COMMIT();

    // ---- top-4 state ----
    float w0=-CUDART_INF_F, w1=-CUDART_INF_F, w2=-CUDART_INF_F, w3=-CUDART_INF_F;
    int   i0=0, i1=0, i2=0, i3=0;

    // corr^T: rows of this warp share (b,h); l = l0 + lane
    const int b = (int)(r0 >> 14);
    const int h = ((int)(r0 >> 11)) & 7;
    const int l = ((int)(r0 & 2047)) + lane;
    float* cA = outC + (long long)b * (64 * 8 * 2048) + (long long)h * 2048 + l;

    // ---- correlation: 2 passes x 32 accumulators, pure register FFMA ----
    #pragma unroll
    for (int p = 0; p < 2; p++) {
        float c[32];
        #pragma unroll
        for (int dd = 0; dd < 32; dd++) c[dd] = 0.f;

        #pragma unroll
        for (int j = 0; j < 64; j++) {
            const float qj = qr[j];
            #pragma unroll
            for (int dd = 0; dd < 32; dd++)
                c[dd] = fmaf(qj, kr[(j + 64 - p * 32 - dd) & 63], c[dd]);
        }

        #pragma unroll
        for (int dd = 0; dd < 32; dd++) {
            const int d = p * 32 + dd;
            const float v = c[dd];
            cA[d * 16384] = v;                   // lanes contiguous in l
            TOPK_INS(v, d);
        }
    }

    // ---- softmax over the 4 weights (w0 is the max) ----
    const float e1 = __expf(w1 - w0), e2 = __expf(w2 - w0), e3 = __expf(w3 - w0);
    const float inv = 1.f / (1.f + e1 + e2 + e3);
    const float t0 = inv, t1 = e1 * inv, t2 = e2 * inv, t3 = e3 * inv;

    // ---- v ready (prefetched behind corr) ----
    CP_WAIT(0);
    __syncwarp();

    // ---- gather + direct float4 V store (L2 merges half-sectors) ----
    {
        const float* vp = Tf + lane * STRS;
        float* outR = outV + off + lane * 64;
        #pragma unroll
        for (int eg = 0; eg < 16; eg++) {
            float4 o;
            #pragma unroll
            for (int s = 0; s < 4; s++) {
                const int e = eg * 4 + s;
                float sa =      t0 * vp[(e + i0) & 63];
                sa = fmaf(t1, vp[(e + i1) & 63], sa);
                sa = fmaf(t2, vp[(e + i2) & 63], sa);
                sa = fmaf(t3, vp[(e + i3) & 63], sa);
                (&o.x)[s] = sa;
            }
            *(float4*)(outR + eg * 4) = o;
        }
    }
}

extern "C" void kernel_launch(void* const* d_in, const int* in_sizes, int n_in,
                              void* d_out, int out_size) {
    const float* q = (const float*)d_in[0];
    const float* k = (const float*)d_in[1];
    const float* v = (const float*)d_in[2];
    float* outV = (float*)d_out;
    float* outC = (float*)d_out + (long long)32 * 8 * 2048 * 64;

    const int rows    = 32 * 8 * 2048;      // 524288
    const int nblocks = rows / 64;          // 8192 blocks, 2 warps (64 rows) each
    autocorr_kernel<<<nblocks, 64>>>(q, k, v, outV, outC);
}